// round 1
// baseline (speedup 1.0000x reference)
#include <cuda_runtime.h>
#include <cuda_bf16.h>

// Problem constants (shapes fixed by the dataset)
#define MAXN 50000
#define MAXE 800000
#define F 128      // input features
#define H 4        // heads
#define C 32       // channels/head  (H*C == F)

// Scratch (device globals; no allocation allowed)
__device__ float g_xw[MAXN * F];        // x @ W      [N, H*C]
__device__ float g_ai[MAXN * H];        // att·xw first half  (source role)
__device__ float g_aj[MAXN * H];        // att·xw second half (dest role)
__device__ float g_p[MAXE * H];         // exp(leaky(alpha)) per edge
__device__ float g_segsum[MAXN * H];    // softmax denominator per (row, h)
__device__ float g_accum[MAXN * F];     // aggregated output [N, H, C]

// ---------------------------------------------------------------------------
// zero scratch that is accumulated into
__global__ void k_zero() {
    int stride = gridDim.x * blockDim.x;
    int t = blockIdx.x * blockDim.x + threadIdx.x;
    for (int i = t; i < MAXN * F; i += stride) g_accum[i] = 0.0f;
    for (int i = t; i < MAXN * H; i += stride) g_segsum[i] = 0.0f;
}

// ---------------------------------------------------------------------------
// GEMM: g_xw = x @ W,  x:[N,128], W:[128,128]
// BM=64 rows per block, full 128 cols, BK=16. 256 threads, 4x8 micro-tile.
#define BM 64
#define BK 16
__global__ void k_gemm(const float* __restrict__ x, const float* __restrict__ w, int N) {
    __shared__ float As[BK][BM];
    __shared__ float Bs[BK][F];
    int tid = threadIdx.x;
    int row0 = blockIdx.x * BM;
    int ty = tid >> 4;        // 0..15 -> 4 rows each
    int tx = tid & 15;        // 0..15 -> 8 cols each

    int ar = tid >> 2;            // 0..63
    int ak = (tid & 3) * 4;       // 0,4,8,12
    int bk = tid >> 4;            // 0..15
    int bj = (tid & 15) * 8;      // 0..120

    float acc[4][8];
#pragma unroll
    for (int i = 0; i < 4; i++)
#pragma unroll
        for (int j = 0; j < 8; j++) acc[i][j] = 0.0f;

    for (int k0 = 0; k0 < F; k0 += BK) {
        // load A tile (transposed into smem)
        float4 av = make_float4(0.f, 0.f, 0.f, 0.f);
        int grow = row0 + ar;
        if (grow < N) av = *(const float4*)&x[grow * F + k0 + ak];
        As[ak + 0][ar] = av.x;
        As[ak + 1][ar] = av.y;
        As[ak + 2][ar] = av.z;
        As[ak + 3][ar] = av.w;
        // load B tile
        float4 b0 = *(const float4*)&w[(k0 + bk) * F + bj];
        float4 b1 = *(const float4*)&w[(k0 + bk) * F + bj + 4];
        *(float4*)&Bs[bk][bj]     = b0;
        *(float4*)&Bs[bk][bj + 4] = b1;
        __syncthreads();

#pragma unroll
        for (int k = 0; k < BK; k++) {
            float a[4], b[8];
#pragma unroll
            for (int i = 0; i < 4; i++) a[i] = As[k][ty * 4 + i];
#pragma unroll
            for (int j = 0; j < 8; j++) b[j] = Bs[k][tx * 8 + j];
#pragma unroll
            for (int i = 0; i < 4; i++)
#pragma unroll
                for (int j = 0; j < 8; j++) acc[i][j] += a[i] * b[j];
        }
        __syncthreads();
    }

#pragma unroll
    for (int i = 0; i < 4; i++) {
        int grow = row0 + ty * 4 + i;
        if (grow < N) {
            float4 v0 = make_float4(acc[i][0], acc[i][1], acc[i][2], acc[i][3]);
            float4 v1 = make_float4(acc[i][4], acc[i][5], acc[i][6], acc[i][7]);
            *(float4*)&g_xw[grow * F + tx * 8]     = v0;
            *(float4*)&g_xw[grow * F + tx * 8 + 4] = v1;
        }
    }
}

// ---------------------------------------------------------------------------
// per-node attention half-dots: a_i[n,h] = xw[n,h,:]·att[h,:C],
//                               a_j[n,h] = xw[n,h,:]·att[h,C:]
__global__ void k_att(const float* __restrict__ att, int N) {
    __shared__ float s_att[H * 2 * C];   // 256 floats
    if (threadIdx.x < H * 2 * C) s_att[threadIdx.x] = att[threadIdx.x];
    __syncthreads();
    int t = blockIdx.x * blockDim.x + threadIdx.x;
    if (t >= N * H) return;
    int n = t >> 2, h = t & 3;
    const float* xr = &g_xw[n * F + h * C];
    const float* a1 = &s_att[h * 2 * C];
    const float* a2 = a1 + C;
    float s1 = 0.f, s2 = 0.f;
#pragma unroll
    for (int c = 0; c < C; c++) {
        float v = xr[c];
        s1 += v * a1[c];
        s2 += v * a2[c];
    }
    g_ai[t] = s1;
    g_aj[t] = s2;
}

// ---------------------------------------------------------------------------
// per-edge: p = exp(leaky(a_i[row] + a_j[col])); segsum[row] += p
// (softmax max-shift skipped: shift-invariant, |alpha| small -> no overflow)
__device__ __forceinline__ float leaky_exp(float a) {
    a = (a >= 0.f) ? a : 0.2f * a;
    return __expf(a);
}

__global__ void k_edge1(const int* __restrict__ ei, int E) {
    int e = blockIdx.x * blockDim.x + threadIdx.x;
    if (e >= E) return;
    int r = ei[e];
    int c = ei[E + e];
    float4 ai = *(const float4*)&g_ai[r * H];
    float4 aj = *(const float4*)&g_aj[c * H];
    float4 p;
    p.x = leaky_exp(ai.x + aj.x);
    p.y = leaky_exp(ai.y + aj.y);
    p.z = leaky_exp(ai.z + aj.z);
    p.w = leaky_exp(ai.w + aj.w);
    *(float4*)&g_p[e * H] = p;
    atomicAdd(&g_segsum[r * H + 0], p.x);
    atomicAdd(&g_segsum[r * H + 1], p.y);
    atomicAdd(&g_segsum[r * H + 2], p.z);
    atomicAdd(&g_segsum[r * H + 3], p.w);
}

// ---------------------------------------------------------------------------
// aggregation: warp per edge.  lane covers 4 consecutive floats (one head slice)
// accum[col, h, :] += (p / segsum[row,h]) * xw[row, h, :]
__global__ void k_edge2(const int* __restrict__ ei, int E) {
    int warp = threadIdx.x >> 5;
    int lane = threadIdx.x & 31;
    int e = blockIdx.x * 8 + warp;
    if (e >= E) return;
    int r = 0, c = 0;
    if (lane == 0) {
        r = ei[e];
        c = ei[E + e];
    }
    r = __shfl_sync(0xffffffffu, r, 0);
    c = __shfl_sync(0xffffffffu, c, 0);
    int h = lane >> 3;                       // 8 lanes per head (8*4 = 32 ch)
    float p = g_p[e * H + h];
    float s = g_segsum[r * H + h];
    float w = p / (s + 1e-16f);
    float4 v = *(const float4*)&g_xw[r * F + lane * 4];
    float* dst = &g_accum[c * F + lane * 4];
    atomicAdd(dst + 0, w * v.x);
    atomicAdd(dst + 1, w * v.y);
    atomicAdd(dst + 2, w * v.z);
    atomicAdd(dst + 3, w * v.w);
}

// ---------------------------------------------------------------------------
// head mean + bias:  out[n,c] = mean_h accum[n,h,c] + bias[c]
__global__ void k_final(const float* __restrict__ bias, float* __restrict__ out, int N) {
    int t = blockIdx.x * blockDim.x + threadIdx.x;
    if (t >= N * C) return;
    int n = t >> 5, c = t & 31;
    const float* a = &g_accum[n * F];
    out[t] = 0.25f * (a[c] + a[c + C] + a[c + 2 * C] + a[c + 3 * C]) + bias[c];
}

// ---------------------------------------------------------------------------
extern "C" void kernel_launch(void* const* d_in, const int* in_sizes, int n_in,
                              void* d_out, int out_size) {
    const float* x    = (const float*)d_in[0];
    const int*   ei   = (const int*)d_in[1];
    const float* w    = (const float*)d_in[2];
    const float* att  = (const float*)d_in[3];
    const float* bias = (const float*)d_in[4];
    float* out = (float*)d_out;

    int N = in_sizes[0] / F;
    int E = in_sizes[1] / 2;

    k_zero<<<1024, 256>>>();
    k_gemm<<<(N + BM - 1) / BM, 256>>>(x, w, N);
    k_att<<<(N * H + 255) / 256, 256>>>(att, N);
    k_edge1<<<(E + 255) / 256, 256>>>(ei, E);
    k_edge2<<<(E + 7) / 8, 256>>>(ei, E);
    k_final<<<(N * C + 255) / 256, 256>>>(bias, out, N);
}

// round 2
// speedup vs baseline: 2.3089x; 2.3089x over previous
#include <cuda_runtime.h>
#include <cuda_bf16.h>

// Problem constants (shapes fixed by the dataset)
#define MAXN 50000
#define MAXE 800000
#define F 128      // input features
#define H 4        // heads
#define C 32       // channels/head  (H*C == F)

// Scratch (device globals; no allocation allowed)
__device__ float g_xw[MAXN * F];        // x @ W      [N, H*C]
__device__ float g_ai[MAXN * H];        // att·xw first half  (source role)
__device__ float g_aj[MAXN * H];        // att·xw second half (dest role)
__device__ float g_p[MAXE * H];         // exp(leaky(alpha)) per edge
__device__ float g_segsum[MAXN * H];    // softmax denominator per (row, h)
__device__ float g_inv[MAXN * H];       // 0.25 / (segsum + 1e-16)

// ---------------------------------------------------------------------------
// vector atomic add (sm_90+): one red op covers 16 bytes
__device__ __forceinline__ void red_add_v4(float* p, float a, float b, float c, float d) {
    asm volatile("red.global.add.v4.f32 [%0], {%1, %2, %3, %4};"
                 :: "l"(p), "f"(a), "f"(b), "f"(c), "f"(d) : "memory");
}

// ---------------------------------------------------------------------------
// init: segsum = 0, out[n,c] = bias[c]  (atomics accumulate into out directly)
__global__ void k_init(const float* __restrict__ bias, float* __restrict__ out, int N) {
    int stride = gridDim.x * blockDim.x;
    int t = blockIdx.x * blockDim.x + threadIdx.x;
    for (int i = t; i < N * C; i += stride) out[i] = bias[i & (C - 1)];
    for (int i = t; i < N * H; i += stride) g_segsum[i] = 0.0f;
}

// ---------------------------------------------------------------------------
// GEMM: g_xw = x @ W,  x:[N,128], W:[128,128]
#define BM 64
#define BK 16
__global__ void k_gemm(const float* __restrict__ x, const float* __restrict__ w, int N) {
    __shared__ float As[BK][BM];
    __shared__ float Bs[BK][F];
    int tid = threadIdx.x;
    int row0 = blockIdx.x * BM;
    int ty = tid >> 4;        // 0..15 -> 4 rows each
    int tx = tid & 15;        // 0..15 -> 8 cols each

    int ar = tid >> 2;            // 0..63
    int ak = (tid & 3) * 4;       // 0,4,8,12
    int bk = tid >> 4;            // 0..15
    int bj = (tid & 15) * 8;      // 0..120

    float acc[4][8];
#pragma unroll
    for (int i = 0; i < 4; i++)
#pragma unroll
        for (int j = 0; j < 8; j++) acc[i][j] = 0.0f;

    for (int k0 = 0; k0 < F; k0 += BK) {
        float4 av = make_float4(0.f, 0.f, 0.f, 0.f);
        int grow = row0 + ar;
        if (grow < N) av = *(const float4*)&x[grow * F + k0 + ak];
        As[ak + 0][ar] = av.x;
        As[ak + 1][ar] = av.y;
        As[ak + 2][ar] = av.z;
        As[ak + 3][ar] = av.w;
        float4 b0 = *(const float4*)&w[(k0 + bk) * F + bj];
        float4 b1 = *(const float4*)&w[(k0 + bk) * F + bj + 4];
        *(float4*)&Bs[bk][bj]     = b0;
        *(float4*)&Bs[bk][bj + 4] = b1;
        __syncthreads();

#pragma unroll
        for (int k = 0; k < BK; k++) {
            float a[4], b[8];
#pragma unroll
            for (int i = 0; i < 4; i++) a[i] = As[k][ty * 4 + i];
#pragma unroll
            for (int j = 0; j < 8; j++) b[j] = Bs[k][tx * 8 + j];
#pragma unroll
            for (int i = 0; i < 4; i++)
#pragma unroll
                for (int j = 0; j < 8; j++) acc[i][j] += a[i] * b[j];
        }
        __syncthreads();
    }

#pragma unroll
    for (int i = 0; i < 4; i++) {
        int grow = row0 + ty * 4 + i;
        if (grow < N) {
            float4 v0 = make_float4(acc[i][0], acc[i][1], acc[i][2], acc[i][3]);
            float4 v1 = make_float4(acc[i][4], acc[i][5], acc[i][6], acc[i][7]);
            *(float4*)&g_xw[grow * F + tx * 8]     = v0;
            *(float4*)&g_xw[grow * F + tx * 8 + 4] = v1;
        }
    }
}

// ---------------------------------------------------------------------------
// per-node attention half-dots
__global__ void k_att(const float* __restrict__ att, int N) {
    __shared__ float s_att[H * 2 * C];   // 256 floats
    if (threadIdx.x < H * 2 * C) s_att[threadIdx.x] = att[threadIdx.x];
    __syncthreads();
    int t = blockIdx.x * blockDim.x + threadIdx.x;
    if (t >= N * H) return;
    int n = t >> 2, h = t & 3;
    const float* xr = &g_xw[n * F + h * C];
    const float* a1 = &s_att[h * 2 * C];
    const float* a2 = a1 + C;
    float s1 = 0.f, s2 = 0.f;
#pragma unroll
    for (int c = 0; c < C; c++) {
        float v = xr[c];
        s1 += v * a1[c];
        s2 += v * a2[c];
    }
    g_ai[t] = s1;
    g_aj[t] = s2;
}

// ---------------------------------------------------------------------------
// per-edge: p = exp(leaky(a_i[row] + a_j[col])); segsum[row] += p (one v4 red)
// (softmax max-shift skipped: shift-invariant, |alpha| small -> no overflow)
__device__ __forceinline__ float leaky_exp(float a) {
    a = (a >= 0.f) ? a : 0.2f * a;
    return __expf(a);
}

__global__ void k_edge1(const int* __restrict__ ei, int E) {
    int e = blockIdx.x * blockDim.x + threadIdx.x;
    if (e >= E) return;
    int r = ei[e];
    int c = ei[E + e];
    float4 ai = *(const float4*)&g_ai[r * H];
    float4 aj = *(const float4*)&g_aj[c * H];
    float4 p;
    p.x = leaky_exp(ai.x + aj.x);
    p.y = leaky_exp(ai.y + aj.y);
    p.z = leaky_exp(ai.z + aj.z);
    p.w = leaky_exp(ai.w + aj.w);
    *(float4*)&g_p[e * H] = p;
    red_add_v4(&g_segsum[r * H], p.x, p.y, p.z, p.w);
}

// ---------------------------------------------------------------------------
// inv[n,h] = 0.25 / (segsum[n,h] + 1e-16)   (folds head-mean factor)
__global__ void k_inv(int N) {
    int t = blockIdx.x * blockDim.x + threadIdx.x;
    if (t >= N * H) return;
    g_inv[t] = 0.25f / (g_segsum[t] + 1e-16f);
}

// ---------------------------------------------------------------------------
// aggregation with head-fold: 8 lanes per edge, 4 edges per warp.
// out[col, c] += sum_h w_h * xw[row, h*32 + c]   (c = lane8*4 .. +3)
__global__ void k_edge2(const int* __restrict__ ei, float* __restrict__ out, int E) {
    int gt = blockIdx.x * blockDim.x + threadIdx.x;
    int e = gt >> 3;                  // 8 lanes per edge
    if (e >= E) return;
    int l8 = gt & 7;                  // channel group 0..7

    int r = __ldg(&ei[e]);
    int c = __ldg(&ei[E + e]);

    float4 p = *(const float4*)&g_p[e * H];
    float4 iv = *(const float4*)&g_inv[r * H];
    float w0 = p.x * iv.x;
    float w1 = p.y * iv.y;
    float w2 = p.z * iv.z;
    float w3 = p.w * iv.w;

    const float* xr = &g_xw[r * F + l8 * 4];
    float4 v0 = *(const float4*)&xr[0];
    float4 v1 = *(const float4*)&xr[C];
    float4 v2 = *(const float4*)&xr[2 * C];
    float4 v3 = *(const float4*)&xr[3 * C];

    float mx = w0 * v0.x + w1 * v1.x + w2 * v2.x + w3 * v3.x;
    float my = w0 * v0.y + w1 * v1.y + w2 * v2.y + w3 * v3.y;
    float mz = w0 * v0.z + w1 * v1.z + w2 * v2.z + w3 * v3.z;
    float mw = w0 * v0.w + w1 * v1.w + w2 * v2.w + w3 * v3.w;

    red_add_v4(&out[c * C + l8 * 4], mx, my, mz, mw);
}

// ---------------------------------------------------------------------------
extern "C" void kernel_launch(void* const* d_in, const int* in_sizes, int n_in,
                              void* d_out, int out_size) {
    const float* x    = (const float*)d_in[0];
    const int*   ei   = (const int*)d_in[1];
    const float* w    = (const float*)d_in[2];
    const float* att  = (const float*)d_in[3];
    const float* bias = (const float*)d_in[4];
    float* out = (float*)d_out;

    int N = in_sizes[0] / F;
    int E = in_sizes[1] / 2;

    k_init<<<1024, 256>>>(bias, out, N);
    k_gemm<<<(N + BM - 1) / BM, 256>>>(x, w, N);
    k_att<<<(N * H + 255) / 256, 256>>>(att, N);
    k_edge1<<<(E + 255) / 256, 256>>>(ei, E);
    k_inv<<<(N * H + 255) / 256, 256>>>(N);
    k_edge2<<<(E * 8 + 255) / 256, 256>>>(ei, out, E);
}

// round 3
// speedup vs baseline: 2.3160x; 1.0031x over previous
#include <cuda_runtime.h>
#include <cuda_bf16.h>

// Problem constants (shapes fixed by the dataset)
#define MAXN 50000
#define MAXE 800000
#define F 128      // input features
#define H 4        // heads
#define C 32       // channels/head  (H*C == F)

// Scratch (device globals; no allocation allowed)
__device__ float g_xw[MAXN * F];        // x @ W      [N, H*C]
__device__ float g_ai[MAXN * H];        // att·xw first half  (source role)
__device__ float g_aj[MAXN * H];        // att·xw second half (dest role)
__device__ float g_p[MAXE * H];         // exp(leaky(alpha)) per edge
__device__ float g_segsum[MAXN * H];    // softmax denominator per (row, h)
__device__ float g_inv[MAXN * H];       // 0.25 / (segsum + 1e-16)

// ---------------------------------------------------------------------------
// vector atomic add (sm_90+): one red op covers 16 bytes
__device__ __forceinline__ void red_add_v4(float* p, float a, float b, float c, float d) {
    asm volatile("red.global.add.v4.f32 [%0], {%1, %2, %3, %4};"
                 :: "l"(p), "f"(a), "f"(b), "f"(c), "f"(d) : "memory");
}

// ---------------------------------------------------------------------------
// init: segsum = 0, out[n,c] = bias[c]  (atomics accumulate into out directly)
__global__ void k_init(const float* __restrict__ bias, float* __restrict__ out, int N) {
    int stride = gridDim.x * blockDim.x;
    int t = blockIdx.x * blockDim.x + threadIdx.x;
    for (int i = t; i < N * C; i += stride) out[i] = bias[i & (C - 1)];
    for (int i = t; i < N * H; i += stride) g_segsum[i] = 0.0f;
}

// ---------------------------------------------------------------------------
// GEMM: g_xw = x @ W,  x:[N,128], W:[128,128]
#define BM 64
#define BK 16
__global__ void k_gemm(const float* __restrict__ x, const float* __restrict__ w, int N) {
    __shared__ float As[BK][BM];
    __shared__ float Bs[BK][F];
    int tid = threadIdx.x;
    int row0 = blockIdx.x * BM;
    int ty = tid >> 4;        // 0..15 -> 4 rows each
    int tx = tid & 15;        // 0..15 -> 8 cols each

    int ar = tid >> 2;            // 0..63
    int ak = (tid & 3) * 4;       // 0,4,8,12
    int bk = tid >> 4;            // 0..15
    int bj = (tid & 15) * 8;      // 0..120

    float acc[4][8];
#pragma unroll
    for (int i = 0; i < 4; i++)
#pragma unroll
        for (int j = 0; j < 8; j++) acc[i][j] = 0.0f;

    for (int k0 = 0; k0 < F; k0 += BK) {
        float4 av = make_float4(0.f, 0.f, 0.f, 0.f);
        int grow = row0 + ar;
        if (grow < N) av = *(const float4*)&x[grow * F + k0 + ak];
        As[ak + 0][ar] = av.x;
        As[ak + 1][ar] = av.y;
        As[ak + 2][ar] = av.z;
        As[ak + 3][ar] = av.w;
        float4 b0 = *(const float4*)&w[(k0 + bk) * F + bj];
        float4 b1 = *(const float4*)&w[(k0 + bk) * F + bj + 4];
        *(float4*)&Bs[bk][bj]     = b0;
        *(float4*)&Bs[bk][bj + 4] = b1;
        __syncthreads();

#pragma unroll
        for (int k = 0; k < BK; k++) {
            float a[4], b[8];
#pragma unroll
            for (int i = 0; i < 4; i++) a[i] = As[k][ty * 4 + i];
#pragma unroll
            for (int j = 0; j < 8; j++) b[j] = Bs[k][tx * 8 + j];
#pragma unroll
            for (int i = 0; i < 4; i++)
#pragma unroll
                for (int j = 0; j < 8; j++) acc[i][j] += a[i] * b[j];
        }
        __syncthreads();
    }

#pragma unroll
    for (int i = 0; i < 4; i++) {
        int grow = row0 + ty * 4 + i;
        if (grow < N) {
            float4 v0 = make_float4(acc[i][0], acc[i][1], acc[i][2], acc[i][3]);
            float4 v1 = make_float4(acc[i][4], acc[i][5], acc[i][6], acc[i][7]);
            *(float4*)&g_xw[grow * F + tx * 8]     = v0;
            *(float4*)&g_xw[grow * F + tx * 8 + 4] = v1;
        }
    }
}

// ---------------------------------------------------------------------------
// per-node attention half-dots
__global__ void k_att(const float* __restrict__ att, int N) {
    __shared__ float s_att[H * 2 * C];   // 256 floats
    if (threadIdx.x < H * 2 * C) s_att[threadIdx.x] = att[threadIdx.x];
    __syncthreads();
    int t = blockIdx.x * blockDim.x + threadIdx.x;
    if (t >= N * H) return;
    int n = t >> 2, h = t & 3;
    const float* xr = &g_xw[n * F + h * C];
    const float* a1 = &s_att[h * 2 * C];
    const float* a2 = a1 + C;
    float s1 = 0.f, s2 = 0.f;
#pragma unroll
    for (int c = 0; c < C; c++) {
        float v = xr[c];
        s1 += v * a1[c];
        s2 += v * a2[c];
    }
    g_ai[t] = s1;
    g_aj[t] = s2;
}

// ---------------------------------------------------------------------------
// per-edge: p = exp(leaky(a_i[row] + a_j[col])); segsum[row] += p (one v4 red)
// (softmax max-shift skipped: shift-invariant, |alpha| small -> no overflow)
__device__ __forceinline__ float leaky_exp(float a) {
    a = (a >= 0.f) ? a : 0.2f * a;
    return __expf(a);
}

__global__ void k_edge1(const int* __restrict__ ei, int E) {
    int e = blockIdx.x * blockDim.x + threadIdx.x;
    if (e >= E) return;
    int r = ei[e];
    int c = ei[E + e];
    float4 ai = *(const float4*)&g_ai[r * H];
    float4 aj = *(const float4*)&g_aj[c * H];
    float4 p;
    p.x = leaky_exp(ai.x + aj.x);
    p.y = leaky_exp(ai.y + aj.y);
    p.z = leaky_exp(ai.z + aj.z);
    p.w = leaky_exp(ai.w + aj.w);
    *(float4*)&g_p[e * H] = p;
    red_add_v4(&g_segsum[r * H], p.x, p.y, p.z, p.w);
}

// ---------------------------------------------------------------------------
// inv[n,h] = 0.25 / (segsum[n,h] + 1e-16)   (folds head-mean factor)
__global__ void k_inv(int N) {
    int t = blockIdx.x * blockDim.x + threadIdx.x;
    if (t >= N * H) return;
    g_inv[t] = 0.25f / (g_segsum[t] + 1e-16f);
}

// ---------------------------------------------------------------------------
// aggregation with head-fold: 8 lanes per edge, 4 edges per warp.
// out[col, c] += sum_h w_h * xw[row, h*32 + c]   (c = lane8*4 .. +3)
__global__ void k_edge2(const int* __restrict__ ei, float* __restrict__ out, int E) {
    int gt = blockIdx.x * blockDim.x + threadIdx.x;
    int e = gt >> 3;                  // 8 lanes per edge
    if (e >= E) return;
    int l8 = gt & 7;                  // channel group 0..7

    int r = __ldg(&ei[e]);
    int c = __ldg(&ei[E + e]);

    float4 p = *(const float4*)&g_p[e * H];
    float4 iv = *(const float4*)&g_inv[r * H];
    float w0 = p.x * iv.x;
    float w1 = p.y * iv.y;
    float w2 = p.z * iv.z;
    float w3 = p.w * iv.w;

    const float* xr = &g_xw[r * F + l8 * 4];
    float4 v0 = *(const float4*)&xr[0];
    float4 v1 = *(const float4*)&xr[C];
    float4 v2 = *(const float4*)&xr[2 * C];
    float4 v3 = *(const float4*)&xr[3 * C];

    float mx = w0 * v0.x + w1 * v1.x + w2 * v2.x + w3 * v3.x;
    float my = w0 * v0.y + w1 * v1.y + w2 * v2.y + w3 * v3.y;
    float mz = w0 * v0.z + w1 * v1.z + w2 * v2.z + w3 * v3.z;
    float mw = w0 * v0.w + w1 * v1.w + w2 * v2.w + w3 * v3.w;

    red_add_v4(&out[c * C + l8 * 4], mx, my, mz, mw);
}

// ---------------------------------------------------------------------------
extern "C" void kernel_launch(void* const* d_in, const int* in_sizes, int n_in,
                              void* d_out, int out_size) {
    const float* x    = (const float*)d_in[0];
    const int*   ei   = (const int*)d_in[1];
    const float* w    = (const float*)d_in[2];
    const float* att  = (const float*)d_in[3];
    const float* bias = (const float*)d_in[4];
    float* out = (float*)d_out;

    int N = in_sizes[0] / F;
    int E = in_sizes[1] / 2;

    k_init<<<1024, 256>>>(bias, out, N);
    k_gemm<<<(N + BM - 1) / BM, 256>>>(x, w, N);
    k_att<<<(N * H + 255) / 256, 256>>>(att, N);
    k_edge1<<<(E + 255) / 256, 256>>>(ei, E);
    k_inv<<<(N * H + 255) / 256, 256>>>(N);
    k_edge2<<<(E * 8 + 255) / 256, 256>>>(ei, out, E);
}

// round 4
// speedup vs baseline: 3.0783x; 1.3291x over previous
#include <cuda_runtime.h>
#include <cuda_fp16.h>
#include <cuda_bf16.h>

// Problem constants (shapes fixed by the dataset)
#define MAXN 50000
#define MAXE 800000
#define F 128      // input features
#define H 4        // heads
#define C 32       // channels/head  (H*C == F)

// Scratch (device globals; no allocation allowed)
__device__ __half g_xwh[MAXN * F];      // x @ W  quantized to fp16 [N, H*C]
__device__ float g_ai[MAXN * H];        // att·xw first half  (source role)
__device__ float g_aj[MAXN * H];        // att·xw second half (dest role)
__device__ float g_p[MAXE * H];         // exp(leaky(alpha)) per edge
__device__ float g_segsum[MAXN * H];    // softmax denominator per (row, h)
__device__ float g_inv[MAXN * H];       // 0.25 / (segsum + 1e-16)

// ---------------------------------------------------------------------------
// vector atomic add (sm_90+): one red op covers 16 bytes
__device__ __forceinline__ void red_add_v4(float* p, float a, float b, float c, float d) {
    asm volatile("red.global.add.v4.f32 [%0], {%1, %2, %3, %4};"
                 :: "l"(p), "f"(a), "f"(b), "f"(c), "f"(d) : "memory");
}

// ---------------------------------------------------------------------------
// init: segsum = 0, out[n,c] = bias[c]  (atomics accumulate into out directly)
__global__ void k_init(const float* __restrict__ bias, float* __restrict__ out, int N) {
    int stride = gridDim.x * blockDim.x;
    int t = blockIdx.x * blockDim.x + threadIdx.x;
    for (int i = t; i < N * C; i += stride) out[i] = bias[i & (C - 1)];
    for (int i = t; i < N * H; i += stride) g_segsum[i] = 0.0f;
}

// ---------------------------------------------------------------------------
// GEMM: xw = x @ W,  x:[N,128], W:[128,128].
// Stores xw as fp16 (g_xwh) and computes the attention half-dots ai/aj in the
// epilogue via 4-lane shuffle reduction (no separate k_att pass).
#define BM 64
#define BK 16
__global__ void k_gemm(const float* __restrict__ x, const float* __restrict__ w,
                       const float* __restrict__ att, int N) {
    __shared__ float As[BK][BM];
    __shared__ float Bs[BK][F];
    __shared__ float s_att[H * 2 * C];   // 256 floats
    int tid = threadIdx.x;
    int row0 = blockIdx.x * BM;
    int ty = tid >> 4;        // 0..15 -> 4 rows each
    int tx = tid & 15;        // 0..15 -> 8 cols each

    s_att[tid] = att[tid];    // 256 threads, 256 floats

    int ar = tid >> 2;            // 0..63
    int ak = (tid & 3) * 4;       // 0,4,8,12
    int bk = tid >> 4;            // 0..15
    int bj = (tid & 15) * 8;      // 0..120

    float acc[4][8];
#pragma unroll
    for (int i = 0; i < 4; i++)
#pragma unroll
        for (int j = 0; j < 8; j++) acc[i][j] = 0.0f;

    for (int k0 = 0; k0 < F; k0 += BK) {
        float4 av = make_float4(0.f, 0.f, 0.f, 0.f);
        int grow = row0 + ar;
        if (grow < N) av = *(const float4*)&x[grow * F + k0 + ak];
        As[ak + 0][ar] = av.x;
        As[ak + 1][ar] = av.y;
        As[ak + 2][ar] = av.z;
        As[ak + 3][ar] = av.w;
        float4 b0 = *(const float4*)&w[(k0 + bk) * F + bj];
        float4 b1 = *(const float4*)&w[(k0 + bk) * F + bj + 4];
        *(float4*)&Bs[bk][bj]     = b0;
        *(float4*)&Bs[bk][bj + 4] = b1;
        __syncthreads();

#pragma unroll
        for (int k = 0; k < BK; k++) {
            float a[4], b[8];
#pragma unroll
            for (int i = 0; i < 4; i++) a[i] = As[k][ty * 4 + i];
#pragma unroll
            for (int j = 0; j < 8; j++) b[j] = Bs[k][tx * 8 + j];
#pragma unroll
            for (int i = 0; i < 4; i++)
#pragma unroll
                for (int j = 0; j < 8; j++) acc[i][j] += a[i] * b[j];
        }
        __syncthreads();
    }

    // epilogue: store fp16 xw + attention half-dots
    int h  = tx >> 2;             // head for this thread's 8 columns
    int c0 = (tx & 3) * 8;        // channel offset within head
    const float* a1 = &s_att[h * 2 * C];        // first half
    const float* a2 = a1 + C;                   // second half

#pragma unroll
    for (int i = 0; i < 4; i++) {
        int grow = row0 + ty * 4 + i;
        // fp16 store (8 halfs = 16B)
        if (grow < N) {
            __half2 h0 = __floats2half2_rn(acc[i][0], acc[i][1]);
            __half2 h1 = __floats2half2_rn(acc[i][2], acc[i][3]);
            __half2 h2 = __floats2half2_rn(acc[i][4], acc[i][5]);
            __half2 h3 = __floats2half2_rn(acc[i][6], acc[i][7]);
            uint4 pk;
            pk.x = *reinterpret_cast<unsigned*>(&h0);
            pk.y = *reinterpret_cast<unsigned*>(&h1);
            pk.z = *reinterpret_cast<unsigned*>(&h2);
            pk.w = *reinterpret_cast<unsigned*>(&h3);
            *(uint4*)&g_xwh[grow * F + tx * 8] = pk;
        }
        // attention half-dot partials over this thread's 8 columns
        float s1 = 0.f, s2 = 0.f;
#pragma unroll
        for (int j = 0; j < 8; j++) {
            float v = acc[i][j];
            s1 += v * a1[c0 + j];
            s2 += v * a2[c0 + j];
        }
        // reduce across the 4 threads (tx&3 = 0..3) holding this (row, head)
        s1 += __shfl_xor_sync(0xffffffffu, s1, 1);
        s1 += __shfl_xor_sync(0xffffffffu, s1, 2);
        s2 += __shfl_xor_sync(0xffffffffu, s2, 1);
        s2 += __shfl_xor_sync(0xffffffffu, s2, 2);
        if ((tx & 3) == 0 && grow < N) {
            g_ai[grow * H + h] = s1;
            g_aj[grow * H + h] = s2;
        }
    }
}

// ---------------------------------------------------------------------------
// per-edge: p = exp(leaky(a_i[row] + a_j[col])); segsum[row] += p (one v4 red)
// (softmax max-shift skipped: shift-invariant, |alpha| small -> no overflow)
__device__ __forceinline__ float leaky_exp(float a) {
    a = (a >= 0.f) ? a : 0.2f * a;
    return __expf(a);
}

__global__ void k_edge1(const int* __restrict__ ei, int E) {
    int e = blockIdx.x * blockDim.x + threadIdx.x;
    if (e >= E) return;
    int r = ei[e];
    int c = ei[E + e];
    float4 ai = *(const float4*)&g_ai[r * H];
    float4 aj = *(const float4*)&g_aj[c * H];
    float4 p;
    p.x = leaky_exp(ai.x + aj.x);
    p.y = leaky_exp(ai.y + aj.y);
    p.z = leaky_exp(ai.z + aj.z);
    p.w = leaky_exp(ai.w + aj.w);
    *(float4*)&g_p[e * H] = p;
    red_add_v4(&g_segsum[r * H], p.x, p.y, p.z, p.w);
}

// ---------------------------------------------------------------------------
// inv[n,h] = 0.25 / (segsum[n,h] + 1e-16)   (folds head-mean factor)
__global__ void k_inv(int N) {
    int t = blockIdx.x * blockDim.x + threadIdx.x;
    if (t >= N * H) return;
    g_inv[t] = 0.25f / (g_segsum[t] + 1e-16f);
}

// ---------------------------------------------------------------------------
// aggregation with head-fold: 8 lanes per edge, 4 edges per warp.
// out[col, c] += sum_h w_h * xw[row, h*32 + c]   (c = lane8*4 .. +3)
// xw gathered as fp16 (half the bytes of fp32).
__global__ void k_edge2(const int* __restrict__ ei, float* __restrict__ out, int E) {
    int gt = blockIdx.x * blockDim.x + threadIdx.x;
    int e = gt >> 3;                  // 8 lanes per edge
    if (e >= E) return;
    int l8 = gt & 7;                  // channel group 0..7

    int r = __ldg(&ei[e]);
    int c = __ldg(&ei[E + e]);

    float4 p = *(const float4*)&g_p[e * H];
    float4 iv = *(const float4*)&g_inv[r * H];
    float w0 = p.x * iv.x;
    float w1 = p.y * iv.y;
    float w2 = p.z * iv.z;
    float w3 = p.w * iv.w;

    const __half* xr = &g_xwh[r * F + l8 * 4];
    uint2 u0 = *(const uint2*)&xr[0];
    uint2 u1 = *(const uint2*)&xr[C];
    uint2 u2 = *(const uint2*)&xr[2 * C];
    uint2 u3 = *(const uint2*)&xr[3 * C];

    float2 v0a = __half22float2(*reinterpret_cast<__half2*>(&u0.x));
    float2 v0b = __half22float2(*reinterpret_cast<__half2*>(&u0.y));
    float2 v1a = __half22float2(*reinterpret_cast<__half2*>(&u1.x));
    float2 v1b = __half22float2(*reinterpret_cast<__half2*>(&u1.y));
    float2 v2a = __half22float2(*reinterpret_cast<__half2*>(&u2.x));
    float2 v2b = __half22float2(*reinterpret_cast<__half2*>(&u2.y));
    float2 v3a = __half22float2(*reinterpret_cast<__half2*>(&u3.x));
    float2 v3b = __half22float2(*reinterpret_cast<__half2*>(&u3.y));

    float mx = w0 * v0a.x + w1 * v1a.x + w2 * v2a.x + w3 * v3a.x;
    float my = w0 * v0a.y + w1 * v1a.y + w2 * v2a.y + w3 * v3a.y;
    float mz = w0 * v0b.x + w1 * v1b.x + w2 * v2b.x + w3 * v3b.x;
    float mw = w0 * v0b.y + w1 * v1b.y + w2 * v2b.y + w3 * v3b.y;

    red_add_v4(&out[c * C + l8 * 4], mx, my, mz, mw);
}

// ---------------------------------------------------------------------------
extern "C" void kernel_launch(void* const* d_in, const int* in_sizes, int n_in,
                              void* d_out, int out_size) {
    const float* x    = (const float*)d_in[0];
    const int*   ei   = (const int*)d_in[1];
    const float* w    = (const float*)d_in[2];
    const float* att  = (const float*)d_in[3];
    const float* bias = (const float*)d_in[4];
    float* out = (float*)d_out;

    int N = in_sizes[0] / F;
    int E = in_sizes[1] / 2;

    k_init<<<1024, 256>>>(bias, out, N);
    k_gemm<<<(N + BM - 1) / BM, 256>>>(x, w, att, N);
    k_edge1<<<(E + 255) / 256, 256>>>(ei, E);
    k_inv<<<(N * H + 255) / 256, 256>>>(N);
    k_edge2<<<(E * 8 + 255) / 256, 256>>>(ei, out, E);
}